// round 1
// baseline (speedup 1.0000x reference)
#include <cuda_runtime.h>
#include <cfloat>

#define NN 128

// For row i, column j (j>=i), offset o=j-i is in the sparse set iff:
//   k = max(0, floor(log2(o)) - 3)   (group: o<16 ->0, <32 ->1, <64 ->2, else 3)
//   ((o+1) & ((1<<k)-1)) == 0  &&  (i & ((1<<k)-1)) == 0
// o==0 (diagonal) yields k=0 -> true, so the diagonal is covered too.
__device__ __forceinline__ float sel_val(int i, int j, float m) {
    if (j < i) return 0.0f;
    int o = j - i;
    int fl = 31 - __clz(o | 1);          // floor(log2(max(o,1)))
    int k = fl - 3;
    k = k < 0 ? 0 : k;
    unsigned msk = (1u << k) - 1u;
    bool nz = (((unsigned)(o + 1) & msk) == 0u) && (((unsigned)i & msk) == 0u);
    return nz ? m : 0.0f;
}

__global__ void __launch_bounds__(256)
sparse_maxpool_kernel(const float* __restrict__ x, float* __restrict__ out) {
    __shared__ __align__(16) float xs[NN];

    const int bd   = blockIdx.x;            // one (b,d) pair per block
    const int t    = threadIdx.x;
    const int warp = t >> 5;                 // 8 warps
    const int lane = t & 31;

    // Load this (b,d)'s x row once (32 x float4 = 128 floats)
    if (t < 32) {
        ((float4*)xs)[t] = ((const float4*)(x + (size_t)bd * NN))[t];
    }
    __syncthreads();

    float* outb = out + (size_t)bd * (NN * NN);
    const float4 xv = ((const float4*)xs)[lane];   // columns 4*lane .. 4*lane+3
    const int jb = lane << 2;

    // Each warp computes 16 full rows; each row = one coalesced 512B store.
    #pragma unroll 1
    for (int r = 0; r < 16; ++r) {
        const int i = (warp << 4) + r;

        // Masked values: contribute only columns j >= i
        float v0 = (jb + 0 >= i) ? xv.x : -FLT_MAX;
        float v1 = (jb + 1 >= i) ? xv.y : -FLT_MAX;
        float v2 = (jb + 2 >= i) ? xv.z : -FLT_MAX;
        float v3 = (jb + 3 >= i) ? xv.w : -FLT_MAX;

        // Local inclusive prefix-max over the 4 elements
        float p0 = v0;
        float p1 = fmaxf(p0, v1);
        float p2 = fmaxf(p1, v2);
        float p3 = fmaxf(p2, v3);

        // Warp inclusive max-scan over block maxima (p3)
        float s = p3;
        #pragma unroll
        for (int d = 1; d < 32; d <<= 1) {
            float u = __shfl_up_sync(0xffffffffu, s, d);
            if (lane >= d) s = fmaxf(s, u);
        }
        // Exclusive prefix for this lane
        float excl = __shfl_up_sync(0xffffffffu, s, 1);
        if (lane == 0) excl = -FLT_MAX;

        // prefix_max(x, start=i)[j] for j = jb..jb+3
        float m0 = fmaxf(excl, p0);
        float m1 = fmaxf(excl, p1);
        float m2 = fmaxf(excl, p2);
        float m3 = fmaxf(excl, p3);

        float4 o4;
        o4.x = sel_val(i, jb + 0, m0);
        o4.y = sel_val(i, jb + 1, m1);
        o4.z = sel_val(i, jb + 2, m2);
        o4.w = sel_val(i, jb + 3, m3);

        ((float4*)(outb + (size_t)i * NN))[lane] = o4;
    }
}

extern "C" void kernel_launch(void* const* d_in, const int* in_sizes, int n_in,
                              void* d_out, int out_size) {
    const float* x = (const float*)d_in[0];
    float* out = (float*)d_out;
    // x: [16, 256, 128] -> 4096 (b,d) rows; out: [16, 256, 128, 128]
    const int n_bd = in_sizes[0] / NN;     // 4096
    sparse_maxpool_kernel<<<n_bd, 256>>>(x, out);
}

// round 2
// speedup vs baseline: 1.6896x; 1.6896x over previous
#include <cuda_runtime.h>
#include <cfloat>

#define NN 128

// Ti(k) = 16 << min(3, ctz(base+k)) with base ≡ 0 (mod 16)  => depends only on k=i&15.
__device__ __forceinline__ constexpr int ti_of(int k) {
    return (k == 0 || k == 8) ? 128 : (k & 1) ? 16 : (k & 2) ? 32 : 64;
}

__global__ void __launch_bounds__(256)
sparse_maxpool_kernel(const float* __restrict__ x, float* __restrict__ out) {
    const int bd   = blockIdx.x;            // one (b,d) pair per block
    const int warp = threadIdx.x >> 5;      // 8 warps, warp w owns rows [16w, 16w+15]
    const int lane = threadIdx.x & 31;
    const int jb   = lane << 2;             // this lane's 4 columns: jb..jb+3
    const int base = warp << 4;
    const int srcq = base >> 2;             // lane index holding x[base..base+3]

    // Every lane loads its 4 columns of x (512B row; L1-broadcast across warps).
    const float4 xv = __ldg(((const float4*)(x + (size_t)bd * NN)) + lane);

    // Per-element column thresholds: Tj = 16 << min(3, ctz(j+1)), loop-invariant.
    const int Tj0 = 16 << min(3, __ffs(jb + 1) - 1);
    const int Tj1 = 16 << min(3, __ffs(jb + 2) - 1);
    const int Tj2 = 16 << min(3, __ffs(jb + 3) - 1);
    const int Tj3 = 16 << min(3, __ffs(jb + 4) - 1);

    // Init m_e = max(x[base+16 .. j_e]) for j_e >= base+16, else -inf.
    // (base+16 is a multiple of 4, so the keep-mask is uniform within a lane.)
    float m0, m1, m2, m3;
    {
        const bool keep = (lane >= srcq + 4);
        float v0 = keep ? xv.x : -FLT_MAX;
        float v1 = keep ? xv.y : -FLT_MAX;
        float v2 = keep ? xv.z : -FLT_MAX;
        float v3 = keep ? xv.w : -FLT_MAX;
        float p0 = v0;
        float p1 = fmaxf(p0, v1);
        float p2 = fmaxf(p1, v2);
        float p3 = fmaxf(p2, v3);
        float s = p3;
        #pragma unroll
        for (int d = 1; d < 32; d <<= 1) {
            float u = __shfl_up_sync(0xffffffffu, s, d);
            if (lane >= d) s = fmaxf(s, u);
        }
        float excl = __shfl_up_sync(0xffffffffu, s, 1);
        if (lane == 0) excl = -FLT_MAX;
        m0 = fmaxf(excl, p0);
        m1 = fmaxf(excl, p1);
        m2 = fmaxf(excl, p2);
        m3 = fmaxf(excl, p3);
    }

    float* orow = out + (size_t)bd * (NN * NN) + (size_t)(base + 15) * NN;

    #pragma unroll
    for (int k = 15; k >= 0; --k) {
        const int i = base + k;

        // Broadcast x[i]: component k&3 of lane srcq + (k>>2)  (compile-time select).
        const float xc = ((k & 3) == 0) ? xv.x : ((k & 3) == 1) ? xv.y
                                        : ((k & 3) == 2) ? xv.z : xv.w;
        const float xi = __shfl_sync(0xffffffffu, xc, srcq + (k >> 2));

        // m(i,j) = max(x[i], m(i+1,j)); exact reset at j == i.
        m0 = fmaxf(xi, m0);
        m1 = fmaxf(xi, m1);
        m2 = fmaxf(xi, m2);
        m3 = fmaxf(xi, m3);
        const bool hit = (lane == srcq + (k >> 2));
        if ((k & 3) == 0)      m0 = hit ? xi : m0;
        else if ((k & 3) == 1) m1 = hit ? xi : m1;
        else if ((k & 3) == 2) m2 = hit ? xi : m2;
        else                   m3 = hit ? xi : m3;

        // Sparse mask: nonzero ⇔ (unsigned)(j-i) < min(Ti, Tj).
        const unsigned o0 = (unsigned)(jb + 0 - i);
        const unsigned o1 = (unsigned)(jb + 1 - i);
        const unsigned o2 = (unsigned)(jb + 2 - i);
        const unsigned o3 = (unsigned)(jb + 3 - i);

        constexpr_helper:;
        const int TiK = ti_of(k);  // compile-time constant per unrolled row
        float4 o4;
        if (TiK == 16) {           // odd rows: Tj >= 16 always => T = 16
            o4.x = (o0 < 16u) ? m0 : 0.0f;
            o4.y = (o1 < 16u) ? m1 : 0.0f;
            o4.z = (o2 < 16u) ? m2 : 0.0f;
            o4.w = (o3 < 16u) ? m3 : 0.0f;
        } else if (TiK == 128) {   // i ≡ 0 (mod 8): T = Tj
            o4.x = (o0 < (unsigned)Tj0) ? m0 : 0.0f;
            o4.y = (o1 < (unsigned)Tj1) ? m1 : 0.0f;
            o4.z = (o2 < (unsigned)Tj2) ? m2 : 0.0f;
            o4.w = (o3 < (unsigned)Tj3) ? m3 : 0.0f;
        } else {
            o4.x = (o0 < (unsigned)min(TiK, Tj0)) ? m0 : 0.0f;
            o4.y = (o1 < (unsigned)min(TiK, Tj1)) ? m1 : 0.0f;
            o4.z = (o2 < (unsigned)min(TiK, Tj2)) ? m2 : 0.0f;
            o4.w = (o3 < (unsigned)min(TiK, Tj3)) ? m3 : 0.0f;
        }

        __stcs((float4*)(orow + jb), o4);  // streaming store: output never re-read
        orow -= NN;
    }
}

extern "C" void kernel_launch(void* const* d_in, const int* in_sizes, int n_in,
                              void* d_out, int out_size) {
    const float* x = (const float*)d_in[0];
    float* out = (float*)d_out;
    const int n_bd = in_sizes[0] / NN;  // 16*256 = 4096 (b,d) rows
    sparse_maxpool_kernel<<<n_bd, 256>>>(x, out);
}